// round 17
// baseline (speedup 1.0000x reference)
#include <cuda_runtime.h>
#include <cstdint>

// CapsNet dynamic routing, fused, f32x2-packed over the OD dimension.
// b_t = u * Vsum so u (189 MB) is never materialized.
// Thread = (batch, d-pair); 32 input-caps in 2 smem chunks, s[o] (f32x2) in
// registers, W pre-transposed so LDS.128 yields packed pairs. x stored in
// smem PRE-DUPLICATED as (v,v) f32x2 pairs (no per-iter pack MOVs).
// Softmax exp = QUADRATIC Taylor in packed FMA (|z| small).
// Inter-pass squash computed cooperatively in each pass's prologue.

namespace {
constexpr int B_  = 256;
constexpr int IC_ = 1152;
constexpr int ID_ = 8;
constexpr int OC_ = 10;
constexpr int OD_ = 16;
constexpr int SOD = B_ * OC_ * OD_;   // 40960, layout [b][o][d]

constexpr int IBLK = 16;              // i's per smem chunk
constexpr int NCHK = 2;               // chunks per CTA
constexpr int BCH  = 64;              // batches per CTA
constexpr int NT   = 512;             // 8 dpairs x 64 b
constexpr int GX   = IC_ / (IBLK * NCHK);  // 36
constexpr int GY   = B_ / BCH;             // 4

constexpr int W_TILE_F = IBLK * OC_ * OD_ * ID_;  // 20480 floats (80 KB)
constexpr int XDS = 65;                            // ulonglong2 stride (pad)
constexpr int XD_E = IBLK * 4 * XDS;               // 4160 ulonglong2 entries
constexpr int XD_OFF_F = W_TILE_F;                 // float offset of XD
constexpr int VS_OFF_F = W_TILE_F + XD_E * 4;      // 37120 floats
constexpr int SMEMB = (VS_OFF_F + 10240) * 4;      // 189440 B
constexpr int WT_ELEMS = IC_ * OC_ * OD_ * ID_;    // 1474560
}

typedef unsigned long long ull;

__device__ __align__(16) float g_Wt[WT_ELEMS];  // [i][o][dp][k][dl]
__device__ __align__(16) float g_s[3][SOD];     // [b][o][d]

__device__ __forceinline__ float fast_rcp(float x) {
    float y; asm("rcp.approx.ftz.f32 %0, %1;" : "=f"(y) : "f"(x)); return y;
}
__device__ __forceinline__ float fast_rsqrt(float x) {
    float y; asm("rsqrt.approx.ftz.f32 %0, %1;" : "=f"(y) : "f"(x)); return y;
}
__device__ __forceinline__ ull pack2(float lo, float hi) {
    ull r; asm("mov.b64 %0, {%1, %2};" : "=l"(r) : "f"(lo), "f"(hi)); return r;
}
__device__ __forceinline__ void unpack2(ull v, float& lo, float& hi) {
    asm("mov.b64 {%0, %1}, %2;" : "=f"(lo), "=f"(hi) : "l"(v));
}
__device__ __forceinline__ ull fma2(ull a, ull b, ull c) {
    ull d; asm("fma.rn.f32x2 %0, %1, %2, %3;" : "=l"(d) : "l"(a), "l"(b), "l"(c)); return d;
}
__device__ __forceinline__ ull mul2(ull a, ull b) {
    ull d; asm("mul.rn.f32x2 %0, %1, %2;" : "=l"(d) : "l"(a), "l"(b)); return d;
}
__device__ __forceinline__ ull add2(ull a, ull b) {
    ull d; asm("add.rn.f32x2 %0, %1, %2;" : "=l"(d) : "l"(a), "l"(b)); return d;
}

// Transpose W[i][o][d][k] -> g_Wt[i][o][dp][k][dl], zero accumulators.
__global__ void prepack_zero_kernel(const float* __restrict__ W) {
    int e = blockIdx.x * 512 + threadIdx.x;
    if (e < SOD) {
        g_s[0][e] = 0.f; g_s[1][e] = 0.f; g_s[2][e] = 0.f;
    }
    if (e < WT_ELEMS) {
        int io = e >> 7;          // 128 floats per (i,o)
        int r  = e & 127;
        int dp = r >> 4;
        int k  = (r >> 1) & 7;
        int dl = r & 1;
        g_Wt[e] = W[(io * OD_ + 2 * dp + dl) * ID_ + k];
    }
}

// Routing pass PASS = 0,1,2. Grid (36, 4), block 512 = 8 dpair x 64 b.
// Warp = fixed dpair, 32 batches -> every W smem read is a broadcast.
// PASS>0: prologue cooperatively builds Vs = sum squash(g_s[tau]) in smem.
template<int PASS>
__global__ __launch_bounds__(NT) void route_kernel(
    const float* __restrict__ x)   // [B, IC, ID]
{
    extern __shared__ float sm[];
    float* Wsm = sm;                                        // 80 KB
    ulonglong2* XD = reinterpret_cast<ulonglong2*>(sm + XD_OFF_F); // [ikp(pad)][b]
    ull* Vs = reinterpret_cast<ull*>(sm + VS_OFF_F);        // [o][dp][b]

    const int t   = threadIdx.x;
    const int dp  = t >> 6;         // 0..7
    const int bl  = t & 63;         // 0..63 (warp: 32 consecutive bl, same dp)
    const int b0  = blockIdx.y * BCH;
    const int b   = b0 + bl;

    // ---- prologue: cooperative squash of prior passes into smem Vs ----
    if (PASS > 0) {
        for (int r = t; r < BCH * OC_; r += NT) {           // 640 rows
            int bb = r / OC_;
            int o  = r - bb * OC_;
            size_t gid = (size_t)(b0 + bb) * OC_ + o;
            float v[OD_];
#pragma unroll
            for (int d = 0; d < OD_; d++) v[d] = 0.f;
#pragma unroll
            for (int tau = 0; tau < PASS; tau++) {
                const float4* s4 = reinterpret_cast<const float4*>(
                    g_s[tau] + gid * OD_);
                float4 q0 = s4[0], q1 = s4[1], q2 = s4[2], q3 = s4[3];
                float l2 = q0.x * q0.x;
                l2 = fmaf(q0.y, q0.y, l2); l2 = fmaf(q0.z, q0.z, l2);
                l2 = fmaf(q0.w, q0.w, l2); l2 = fmaf(q1.x, q1.x, l2);
                l2 = fmaf(q1.y, q1.y, l2); l2 = fmaf(q1.z, q1.z, l2);
                l2 = fmaf(q1.w, q1.w, l2); l2 = fmaf(q2.x, q2.x, l2);
                l2 = fmaf(q2.y, q2.y, l2); l2 = fmaf(q2.z, q2.z, l2);
                l2 = fmaf(q2.w, q2.w, l2); l2 = fmaf(q3.x, q3.x, l2);
                l2 = fmaf(q3.y, q3.y, l2); l2 = fmaf(q3.z, q3.z, l2);
                l2 = fmaf(q3.w, q3.w, l2);
                // squash coef = ||s|| / (1 + ||s||^2)
                float cf = l2 * fast_rsqrt(l2) * fast_rcp(1.f + l2);
                v[0]  = fmaf(q0.x, cf, v[0]);  v[1]  = fmaf(q0.y, cf, v[1]);
                v[2]  = fmaf(q0.z, cf, v[2]);  v[3]  = fmaf(q0.w, cf, v[3]);
                v[4]  = fmaf(q1.x, cf, v[4]);  v[5]  = fmaf(q1.y, cf, v[5]);
                v[6]  = fmaf(q1.z, cf, v[6]);  v[7]  = fmaf(q1.w, cf, v[7]);
                v[8]  = fmaf(q2.x, cf, v[8]);  v[9]  = fmaf(q2.y, cf, v[9]);
                v[10] = fmaf(q2.z, cf, v[10]); v[11] = fmaf(q2.w, cf, v[11]);
                v[12] = fmaf(q3.x, cf, v[12]); v[13] = fmaf(q3.y, cf, v[13]);
                v[14] = fmaf(q3.z, cf, v[14]); v[15] = fmaf(q3.w, cf, v[15]);
            }
#pragma unroll
            for (int d2 = 0; d2 < 8; d2++)
                Vs[(o * 8 + d2) * 64 + bb] = pack2(v[2 * d2], v[2 * d2 + 1]);
        }
    }

    ull s[OC_];
    const ull zz  = pack2(0.f, 0.f);
    const ull ONE = pack2(1.f, 1.f);
    const ull C12 = pack2(0.5f, 0.5f);
#pragma unroll
    for (int o = 0; o < OC_; o++) s[o] = zz;

    for (int c = 0; c < NCHK; c++) {
        const int i0 = blockIdx.x * (IBLK * NCHK) + c * IBLK;
        if (c) __syncthreads();     // drain readers of previous tiles

        // ---- W tile: straight copy of pre-transposed weights ----
        {
            const float4* src = reinterpret_cast<const float4*>(
                g_Wt + (size_t)i0 * (OC_ * OD_ * ID_));
            float4* dst = reinterpret_cast<float4*>(Wsm);
#pragma unroll
            for (int r = 0; r < W_TILE_F / 4 / NT; r++)   // 10
                dst[t + r * NT] = src[t + r * NT];
        }
        // ---- x tile: pre-duplicated pairs, [i*4+kp (pad 65)][b] ----
        {
#pragma unroll
            for (int r = 0; r < 8; r++) {
                int f  = t + r * NT;                      // 0..4095
                int bb = f >> 6;                          // 0..63
                int cc = f & 63;                          // float2 within row
                int i = cc >> 2, kp = cc & 3;
                float2 v = *(reinterpret_cast<const float2*>(
                    x + ((size_t)(b0 + bb) * IC_ + i0 + i) * ID_) + kp);
                ulonglong2 w;
                w.x = pack2(v.x, v.x);
                w.y = pack2(v.y, v.y);
                XD[(i * 4 + kp) * XDS + bb] = w;
            }
        }
        __syncthreads();   // also publishes prologue's Vs on c==0

        const ulonglong2* W2 = reinterpret_cast<const ulonglong2*>(Wsm);

#pragma unroll 4
        for (int i = 0; i < IBLK; i++) {
            ulonglong2 x01 = XD[(i * 4 + 0) * XDS + bl];
            ulonglong2 x23 = XD[(i * 4 + 1) * XDS + bl];
            ulonglong2 x45 = XD[(i * 4 + 2) * XDS + bl];
            ulonglong2 x67 = XD[(i * 4 + 3) * XDS + bl];

            ull u[OC_];
#pragma unroll
            for (int o = 0; o < OC_; o++) {
                // broadcast LDS.128: two packed W pairs each
                int wb = ((i * OC_ + o) * ID_ + dp) * 4;
                ulonglong2 w01 = W2[wb];
                ulonglong2 w23 = W2[wb + 1];
                ulonglong2 w45 = W2[wb + 2];
                ulonglong2 w67 = W2[wb + 3];
                ull acc = mul2(w01.x, x01.x);
                acc = fma2(w01.y, x01.y, acc);
                acc = fma2(w23.x, x23.x, acc);
                acc = fma2(w23.y, x23.y, acc);
                acc = fma2(w45.x, x45.x, acc);
                acc = fma2(w45.y, x45.y, acc);
                acc = fma2(w67.x, x67.x, acc);
                acc = fma2(w67.y, x67.y, acc);
                u[o] = acc;
            }

            if (PASS == 0) {
#pragma unroll
                for (int o = 0; o < OC_; o++) s[o] = add2(s[o], u[o]);
            } else {
                ull Za = zz, Zb = zz;   // split Z tree for ILP
#pragma unroll
                for (int o = 0; o < OC_; o++) {
                    // z = u*Vsum is tiny: quadratic Taylor exp, packed FMA.
                    ull vp = Vs[(o * 8 + dp) * 64 + bl];
                    ull z = mul2(u[o], vp);
                    ull p = fma2(z, C12, ONE);
                    ull e = fma2(z, p, ONE);
                    if (o & 1) Zb = add2(Zb, e); else Za = add2(Za, e);
                    u[o] = mul2(u[o], e);         // u now holds u*e
                }
                ull Z2 = add2(Za, Zb);
                float Z0, Z1; unpack2(Z2, Z0, Z1);
                ull rp = pack2(fast_rcp(Z0), fast_rcp(Z1));
#pragma unroll
                for (int o = 0; o < OC_; o++) s[o] = fma2(u[o], rp, s[o]);
            }
        }
    }

    // accumulate partial s into global [b][o][d]
    float* sp = g_s[PASS] + ((size_t)b * OC_) * OD_ + 2 * dp;
#pragma unroll
    for (int o = 0; o < OC_; o++) {
        float a0, a1; unpack2(s[o], a0, a1);
        if (PASS == 0) { a0 *= (1.0f / OC_); a1 *= (1.0f / OC_); }
        atomicAdd(sp + o * OD_, a0);
        atomicAdd(sp + o * OD_ + 1, a1);
    }
}

// Final squash: out = squash(g_s[2]) per (b,o) over d.
__global__ void squash_final_kernel(float* __restrict__ out) {
    const float* __restrict__ s = g_s[2];
    int t  = blockIdx.x * 256 + threadIdx.x;   // SOD threads exactly
    int d  = t & 15;
    int bo = t >> 4;
    int idx = bo * OD_ + d;                    // [b][o][d]

    float sv = s[idx];
    float l2 = sv * sv;
#pragma unroll
    for (int off = 8; off > 0; off >>= 1)
        l2 += __shfl_xor_sync(0xffffffffu, l2, off);

    float coef = l2 * fast_rsqrt(l2) * fast_rcp(1.f + l2);
    out[idx] = sv * coef;                      // output [B, OC, OD]
}

extern "C" void kernel_launch(void* const* d_in, const int* in_sizes, int n_in,
                              void* d_out, int out_size) {
    const float* x = (const float*)d_in[0];   // [256,1152,8]
    const float* W = (const float*)d_in[1];   // [1152,10,16,8]
    float* out = (float*)d_out;               // [256,10,16]

    cudaFuncSetAttribute(route_kernel<0>,
                         cudaFuncAttributeMaxDynamicSharedMemorySize, SMEMB);
    cudaFuncSetAttribute(route_kernel<1>,
                         cudaFuncAttributeMaxDynamicSharedMemorySize, SMEMB);
    cudaFuncSetAttribute(route_kernel<2>,
                         cudaFuncAttributeMaxDynamicSharedMemorySize, SMEMB);

    dim3 rg(GX, GY);

    prepack_zero_kernel<<<(WT_ELEMS + 511) / 512, 512>>>(W);
    route_kernel<0><<<rg, NT, SMEMB>>>(x);
    route_kernel<1><<<rg, NT, SMEMB>>>(x);
    route_kernel<2><<<rg, NT, SMEMB>>>(x);
    squash_final_kernel<<<SOD / 256, 256>>>(out);
}